// round 2
// baseline (speedup 1.0000x reference)
#include <cuda_runtime.h>

typedef unsigned long long ull;

#define TX 16
#define NTOT 51840000   // 405*80*80*20

__device__ float g_mask1[6400];
__device__ float g_mask2[6400];

__global__ void mask_prep(const float* __restrict__ a1, const float* __restrict__ a2)
{
    int p = blockIdx.x * blockDim.x + threadIdx.x;
    if (p < 6400) {
        float s1 = 0.f, s2 = 0.f;
        const float* p1 = a1 + p * 20;
        const float* p2 = a2 + p * 20;
        #pragma unroll
        for (int z = 0; z < 20; ++z) { s1 += p1[z]; s2 += p2[z]; }
        g_mask1[p] = fminf(fmaxf(s1, 0.f), 1.f);
        g_mask2[p] = fminf(fmaxf(s2, 0.f), 1.f);
    }
}

__device__ __forceinline__ ull pack2(float lo, float hi) {
    ull r; asm("mov.b64 %0, {%1, %2};" : "=l"(r) : "f"(lo), "f"(hi)); return r;
}
__device__ __forceinline__ void unpack2(ull v, float& lo, float& hi) {
    asm("mov.b64 {%0, %1}, %2;" : "=f"(lo), "=f"(hi) : "l"(v));
}
__device__ __forceinline__ void fma2(ull& d, ull a, ull b) {
    asm("fma.rn.f32x2 %0, %1, %2, %0;" : "+l"(d) : "l"(a), "l"(b));
}

// block: 240 threads = (tx 16) x (zq 5) x (djl 3)
// grid : (x0 5) x (y 80) x (dslice 27), dslice = di*3 + djg, dj = djg*3 + djl
// smem : f2s [c=16][zq=6][o=18][4]  = 6912 floats = 27648 B  (phased over c halves)
__global__ void __launch_bounds__(240, 5) corr_kernel(
    const float* __restrict__ f1, const float* __restrict__ f2, float* __restrict__ out)
{
    extern __shared__ float smem[];
    float* f2s = smem;

    const int x0  = blockIdx.x * TX;
    const int y   = blockIdx.y;
    const int ds  = blockIdx.z;
    const int di  = ds / 3;
    const int djg = ds - di * 3;
    const int y2  = y + di - 4;
    const bool yok = ((unsigned)y2 < 80u);
    const int tid = threadIdx.x;

    const int tx  = tid & 15;
    const int zq  = (tid >> 4) % 5;      // z = 4*zq .. 4*zq+3
    const int djl = tid / 80;            // 0..2
    const int dj  = djg * 3 + djl;
    const int xbase = x0 + djg * 3 - 4;  // o = tx + djl, x2g = xbase + o

    // acc[dk*2 + p]: p=0 -> z pair (4zq,4zq+1), p=1 -> (4zq+2,4zq+3)
    ull acc[10];
    #pragma unroll
    for (int i = 0; i < 10; ++i) acc[i] = 0ull;

    #pragma unroll
    for (int phase = 0; phase < 2; ++phase) {
        if (phase) __syncthreads();
        // ---- load f2 window (16 channels) with spatial + depth zero padding ----
        if (yok) {
            const float* g2 = f2 + phase * 16 * 128000 + y2 * 1600;
            for (int idx = tid; idx < 288; idx += 240) {
                int c = idx / 18, o = idx - c * 18;
                int x2g = xbase + o;
                float* dst = f2s + c * 432 + o * 4;   // [c][q][o][4], q stride 72
                if ((unsigned)x2g < 80u) {
                    const float* row = g2 + c * 128000 + x2g * 20;
                    dst[0] = 0.f; dst[1] = 0.f;                 // zz = 0,1
                    #pragma unroll
                    for (int q = 0; q < 5; ++q) {               // z = 4q..4q+3 -> zz = 4q+2..
                        float4 v = *(const float4*)(row + 4 * q);
                        dst[q * 72 + 2]       = v.x;
                        dst[q * 72 + 3]       = v.y;
                        dst[(q + 1) * 72 + 0] = v.z;
                        dst[(q + 1) * 72 + 1] = v.w;
                    }
                    dst[5 * 72 + 2] = 0.f; dst[5 * 72 + 3] = 0.f;  // zz = 22,23
                } else {
                    #pragma unroll
                    for (int q = 0; q < 6; ++q) {
                        dst[q * 72 + 0] = 0.f; dst[q * 72 + 1] = 0.f;
                        dst[q * 72 + 2] = 0.f; dst[q * 72 + 3] = 0.f;
                    }
                }
            }
        }
        __syncthreads();
        // ---- accumulate 16 channels ----
        if (yok) {
            const float* a_ptr = f1 + phase * 16 * 128000 + y * 1600 + (x0 + tx) * 20 + 4 * zq;
            const float4* bptr = (const float4*)f2s + zq * 18 + (tx + djl);
            #pragma unroll 4
            for (int cl = 0; cl < 16; ++cl) {
                float4 av = __ldg((const float4*)(a_ptr + cl * 128000));
                ull a01 = pack2(av.x, av.y);
                ull a23 = pack2(av.z, av.w);
                float4 b0 = bptr[cl * 108];        // quad zq
                float4 b4 = bptr[cl * 108 + 18];   // quad zq+1
                ull P0 = pack2(b0.x, b0.y);
                ull P1 = pack2(b0.y, b0.z);
                ull P2 = pack2(b0.z, b0.w);
                ull P3 = pack2(b0.w, b4.x);
                ull P4 = pack2(b4.x, b4.y);
                ull P5 = pack2(b4.y, b4.z);
                ull P6 = pack2(b4.z, b4.w);
                fma2(acc[0], a01, P0); fma2(acc[1], a23, P2);   // dk=0
                fma2(acc[2], a01, P1); fma2(acc[3], a23, P3);   // dk=1
                fma2(acc[4], a01, P2); fma2(acc[5], a23, P4);   // dk=2
                fma2(acc[6], a01, P3); fma2(acc[7], a23, P5);   // dk=3
                fma2(acc[8], a01, P4); fma2(acc[9], a23, P6);   // dk=4
            }
        }
    }

    // ---- epilogue: scale + masks + stores ----
    {
        const int x = x0 + tx;
        const float m1 = g_mask1[y * 80 + x];
        const int x2g = xbase + tx + djl;
        const bool spin = yok && ((unsigned)x2g < 80u);
        const float m2v = spin ? g_mask2[y2 * 80 + x2g] : 1.f;
        const float mIn = fminf(m1 * m2v, m1);   // same as clip(m1*m2,0,1) given m1,m2 in [0,1]
        const float inv = 1.f / 32.f;
        #pragma unroll
        for (int dk = 0; dk < 5; ++dk) {
            const int t = dk * 81 + di * 9 + dj;
            const int base = t * 128000 + y * 1600 + x * 20 + 4 * zq;
            float4 cv;
            unpack2(acc[dk * 2 + 0], cv.x, cv.y);
            unpack2(acc[dk * 2 + 1], cv.z, cv.w);
            cv.x *= inv; cv.y *= inv; cv.z *= inv; cv.w *= inv;
            *(float4*)(out + base) = cv;
            float4 mv;
            {
                float* mp = (float*)&mv;
                #pragma unroll
                for (int zl = 0; zl < 4; ++zl) {
                    int z2 = 4 * zq + zl + dk - 2;
                    mp[zl] = (spin && (unsigned)z2 < 20u) ? mIn : m1;
                }
            }
            *(float4*)(out + NTOT + base) = mv;
        }
    }
}

extern "C" void kernel_launch(void* const* d_in, const int* in_sizes, int n_in,
                              void* d_out, int out_size)
{
    (void)in_sizes; (void)n_in; (void)out_size;
    const float* f1 = (const float*)d_in[0];
    const float* a1 = (const float*)d_in[1];
    const float* f2 = (const float*)d_in[2];
    const float* a2 = (const float*)d_in[3];
    float* out = (float*)d_out;

    cudaFuncSetAttribute(corr_kernel, cudaFuncAttributeMaxDynamicSharedMemorySize, 27648);

    mask_prep<<<25, 256>>>(a1, a2);
    corr_kernel<<<dim3(5, 80, 27), 240, 27648>>>(f1, f2, out);
}

// round 3
// speedup vs baseline: 1.1237x; 1.1237x over previous
#include <cuda_runtime.h>

typedef unsigned long long ull;

#define NTOT 51840000   // 405*80*80*20

__device__ float g_mask1[6400];
__device__ float g_mask2[6400];

__global__ void mask_prep(const float* __restrict__ a1, const float* __restrict__ a2)
{
    int p = blockIdx.x * blockDim.x + threadIdx.x;
    if (p < 6400) {
        float s1 = 0.f, s2 = 0.f;
        const float* p1 = a1 + p * 20;
        const float* p2 = a2 + p * 20;
        #pragma unroll
        for (int z = 0; z < 20; ++z) { s1 += p1[z]; s2 += p2[z]; }
        g_mask1[p] = fminf(fmaxf(s1, 0.f), 1.f);
        g_mask2[p] = fminf(fmaxf(s2, 0.f), 1.f);
    }
}

__device__ __forceinline__ ull pack2(float lo, float hi) {
    ull r; asm("mov.b64 %0, {%1, %2};" : "=l"(r) : "f"(lo), "f"(hi)); return r;
}
__device__ __forceinline__ void unpack2(ull v, float& lo, float& hi) {
    asm("mov.b64 {%0, %1}, %2;" : "=f"(lo), "=f"(hi) : "l"(v));
}
__device__ __forceinline__ void fma2(ull& d, ull a, ull b) {
    asm("fma.rn.f32x2 %0, %1, %2, %0;" : "+l"(d) : "l"(a), "l"(b));
}

// Tiling over f2 columns (x2). block: 240 threads = x2c(16) x zq(5) x djg(3)
// grid: (x2b 6, y 80, di 9); dj = djg*3 + jl, x = x2g + 4 - dj
// smem (per 16-channel phase):
//   f1s: [c16][zq5][xl24][4]  = 7680 floats (30720 B), xl: x = x2g0-4+xl
//   f2s: [c16][n6][x2c16][4]  = 6144 floats (24576 B), quad n = s 4n..4n+3, s = z+2 (zero-padded)
__global__ void __launch_bounds__(240, 3) corr_kernel(
    const float* __restrict__ f1, const float* __restrict__ f2, float* __restrict__ out)
{
    extern __shared__ float smem[];
    float* f1s = smem;           // 7680 floats
    float* f2s = smem + 7680;    // 6144 floats

    const int x2b = blockIdx.x;
    const int y   = blockIdx.y;
    const int di  = blockIdx.z;
    const int x2g0 = x2b * 16 - 4;          // x2 of lane 0
    const int y2  = y + di - 4;
    const bool yok = ((unsigned)y2 < 80u);
    const int tid = threadIdx.x;

    const int x2c = tid & 15;
    const int zq  = (tid >> 4) % 5;
    const int djg = tid / 80;
    const int x2g = x2g0 + x2c;

    ull acc[30];
    #pragma unroll
    for (int i = 0; i < 30; ++i) acc[i] = 0ull;

    #pragma unroll
    for (int phase = 0; phase < 2; ++phase) {
        if (phase) __syncthreads();
        if (yok) {
            // ---- f1 tile fill: x range x2g0-4 .. x2g0+19 (24 cols), 16 channels ----
            const float* g1 = f1 + phase * 16 * 128000 + y * 1600;
            for (int idx = tid; idx < 1920; idx += 240) {
                int c  = idx / 120;
                int r  = idx - c * 120;
                int xl = r / 5;
                int q  = r - xl * 5;
                int xg = x2g0 - 4 + xl;
                float4 v = make_float4(0.f, 0.f, 0.f, 0.f);
                if ((unsigned)xg < 80u)
                    v = *(const float4*)(g1 + c * 128000 + xg * 20 + 4 * q);
                ((float4*)f1s)[(c * 5 + q) * 24 + xl] = v;
            }
            // ---- f2 column fill with depth padding (s = z + 2, s 0..23) ----
            const float* g2 = f2 + phase * 16 * 128000 + y2 * 1600;
            for (int idx = tid; idx < 256; idx += 240) {
                int c   = idx >> 4;
                int x2l = idx & 15;
                int x2  = x2g0 + x2l;
                float* dst = f2s + (c * 6 * 16 + x2l) * 4;  // n-stride = 64 floats
                if ((unsigned)x2 < 80u) {
                    const float* src = g2 + c * 128000 + x2 * 20;
                    *(float2*)dst = make_float2(0.f, 0.f);              // s 0,1
                    #pragma unroll
                    for (int m = 0; m < 5; ++m) {
                        float4 v = *(const float4*)(src + 4 * m);       // z 4m..4m+3
                        *(float2*)(dst + m * 64 + 2)       = make_float2(v.x, v.y); // s 4m+2,3
                        *(float2*)(dst + (m + 1) * 64)     = make_float2(v.z, v.w); // s 4m+4,5
                    }
                    *(float2*)(dst + 5 * 64 + 2) = make_float2(0.f, 0.f);  // s 22,23
                } else {
                    #pragma unroll
                    for (int n = 0; n < 6; ++n)
                        *(float4*)(dst + n * 64) = make_float4(0.f, 0.f, 0.f, 0.f);
                }
            }
        }
        __syncthreads();
        if (yok) {
            // a: float4 at [c][zq][xl], xl = x2c + 8 - dj
            const float4* ap = (const float4*)f1s + zq * 24 + (x2c + 8 - djg * 3);
            const float4* bp = (const float4*)f2s + zq * 16 + x2c;
            #pragma unroll 4
            for (int cl = 0; cl < 16; ++cl) {
                float4 b0 = bp[cl * 96];        // quad n = zq
                float4 b4 = bp[cl * 96 + 16];   // quad n = zq+1
                ull P0 = pack2(b0.x, b0.y);
                ull P1 = pack2(b0.y, b0.z);
                ull P2 = pack2(b0.z, b0.w);
                ull P3 = pack2(b0.w, b4.x);
                ull P4 = pack2(b4.x, b4.y);
                ull P5 = pack2(b4.y, b4.z);
                ull P6 = pack2(b4.z, b4.w);
                #pragma unroll
                for (int jl = 0; jl < 3; ++jl) {
                    float4 av = ap[cl * 120 - jl];
                    ull a01 = pack2(av.x, av.y);
                    ull a23 = pack2(av.z, av.w);
                    ull* A = acc + jl * 10;
                    fma2(A[0], a01, P0); fma2(A[1], a23, P2);   // dk=0
                    fma2(A[2], a01, P1); fma2(A[3], a23, P3);   // dk=1
                    fma2(A[4], a01, P2); fma2(A[5], a23, P4);   // dk=2
                    fma2(A[6], a01, P3); fma2(A[7], a23, P5);   // dk=3
                    fma2(A[8], a01, P4); fma2(A[9], a23, P6);   // dk=4
                }
            }
        }
    }

    // ---- epilogue ----
    {
        const bool x2ok = ((unsigned)x2g < 80u);
        const bool spin = yok && x2ok;
        const float m2v = spin ? g_mask2[y2 * 80 + x2g] : 1.f;
        const float inv = 1.f / 32.f;
        #pragma unroll
        for (int jl = 0; jl < 3; ++jl) {
            const int dj = djg * 3 + jl;
            const int x  = x2g + 4 - dj;
            if ((unsigned)x < 80u) {
                const float m1  = g_mask1[y * 80 + x];
                const float mIn = m1 * m2v;
                #pragma unroll
                for (int dk = 0; dk < 5; ++dk) {
                    const int t = dk * 81 + di * 9 + dj;
                    const int base = t * 128000 + y * 1600 + x * 20 + 4 * zq;
                    float4 cv;
                    unpack2(acc[jl * 10 + dk * 2 + 0], cv.x, cv.y);
                    unpack2(acc[jl * 10 + dk * 2 + 1], cv.z, cv.w);
                    cv.x *= inv; cv.y *= inv; cv.z *= inv; cv.w *= inv;
                    *(float4*)(out + base) = cv;
                    float4 mv;
                    {
                        float* mp = (float*)&mv;
                        #pragma unroll
                        for (int zl = 0; zl < 4; ++zl) {
                            int z2 = 4 * zq + zl + dk - 2;
                            mp[zl] = (spin && (unsigned)z2 < 20u) ? mIn : m1;
                        }
                    }
                    *(float4*)(out + NTOT + base) = mv;
                }
            }
        }
    }
}

extern "C" void kernel_launch(void* const* d_in, const int* in_sizes, int n_in,
                              void* d_out, int out_size)
{
    (void)in_sizes; (void)n_in; (void)out_size;
    const float* f1 = (const float*)d_in[0];
    const float* a1 = (const float*)d_in[1];
    const float* f2 = (const float*)d_in[2];
    const float* a2 = (const float*)d_in[3];
    float* out = (float*)d_out;

    cudaFuncSetAttribute(corr_kernel, cudaFuncAttributeMaxDynamicSharedMemorySize, 55296);

    mask_prep<<<25, 256>>>(a1, a2);
    corr_kernel<<<dim3(6, 80, 9), 240, 55296>>>(f1, f2, out);
}